// round 6
// baseline (speedup 1.0000x reference)
#include <cuda_runtime.h>

#define NTOK   8192      // T*B = 256*32
#define D      128
#define NEXP   9
#define MTILE  64
#define BT     256       // bucket kernel threads

typedef unsigned long long ull;

__device__ int g_counts[NEXP];
__device__ int g_buckets[NEXP * NTOK];

// ---- packed f32x2 helpers (sm_100+ PTX) ----
__device__ __forceinline__ ull pk(float lo, float hi) {
    ull r; asm("mov.b64 %0,{%1,%2};" : "=l"(r) : "f"(lo), "f"(hi)); return r;
}
__device__ __forceinline__ float2 unpk(ull v) {
    float2 r; asm("mov.b64 {%0,%1},%2;" : "=f"(r.x), "=f"(r.y) : "l"(v)); return r;
}
__device__ __forceinline__ ull ffma2(ull a, ull b, ull c) {
    ull d; asm("fma.rn.f32x2 %0,%1,%2,%3;" : "=l"(d) : "l"(a), "l"(b), "l"(c)); return d;
}

// ---- single-block deterministic bucketing: counts + rank scatter, no atomics ----
__global__ __launch_bounds__(BT) void bucket_kernel(const int* __restrict__ positions) {
    __shared__ int cnts[NEXP * BT];
    __shared__ int pfx[NEXP * BT];
    const int t = threadIdx.x;

    #pragma unroll
    for (int e = 0; e < NEXP; e++) cnts[e * BT + t] = 0;
    __syncthreads();

    const int base_tok = t * 32;   // 8192 / 256
    #pragma unroll
    for (int i = 0; i < 32; i++) {
        int p = positions[base_tok + i];
        int r = min(max(p, 0), NEXP - 1);
        cnts[r * BT + t]++;
    }
    __syncthreads();

    // exclusive prefix per expert (9 threads, serial over 256 — cheap)
    if (t < NEXP) {
        int run = 0;
        #pragma unroll 8
        for (int i = 0; i < BT; i++) {
            int v = cnts[t * BT + i];
            pfx[t * BT + i] = run;
            run += v;
        }
        g_counts[t] = run;
    }
    __syncthreads();

    // rank-ordered scatter (deterministic; order within bucket irrelevant anyway)
    #pragma unroll
    for (int i = 0; i < 32; i++) {
        int tok = base_tok + i;
        int p = positions[tok];
        int r = min(max(p, 0), NEXP - 1);
        int slot = pfx[r * BT + t]++;
        g_buckets[r * NTOK + slot] = tok;
    }
}

// ---- grouped GEMM, f32x2 packed-FMA mainloop ----
// Y[m][n] = sum_k X[m][k] * W[e][k][n] + b[e][n]
// Ws: [128][128] fp32 (64KB); Xs: [k][m] with kb-XOR swizzle on m bits [3:4] (32KB).
__global__ __launch_bounds__(256) void gemm_kernel(
    const float* __restrict__ X, const float* __restrict__ W,
    const float* __restrict__ Bv, float* __restrict__ Y)
{
    extern __shared__ float smem[];
    float* Ws = smem;                         // D*D
    float* Xs = smem + D * D;                 // D*MTILE
    int*  idxs = (int*)(smem + D * D + D * MTILE);

    const int e     = blockIdx.x;
    const int tile  = blockIdx.y;
    const int count = g_counts[e];
    const int m0g   = tile * MTILE;
    if (m0g >= count) return;
    const int mvalid = min(MTILE, count - m0g);
    const int tid = threadIdx.x;

    if (tid < MTILE)
        idxs[tid] = (tid < mvalid) ? g_buckets[e * NTOK + m0g + tid] : -1;

    // stage W[e]: 16 float4 per thread, coalesced
    {
        const float4* Wg = (const float4*)(W + (size_t)e * D * D);
        float4* Ws4 = (float4*)Ws;
        #pragma unroll
        for (int i = 0; i < 16; i++)
            Ws4[tid + i * 256] = Wg[tid + i * 256];
    }
    __syncthreads();

    // stage X rows transposed into Xs[k][m^swz]; 4 threads per token row
    {
        const int m  = tid >> 2;
        const int kb = (tid & 3) * 32;
        const int swz = (tid & 3) << 3;       // (k>>5)<<3 for this thread's k range
        const int ms = m ^ swz;
        const int t = idxs[m];
        if (t >= 0) {
            const float4* xr = (const float4*)(X + (size_t)t * D + kb);
            #pragma unroll
            for (int q = 0; q < 8; q++) {
                float4 v = xr[q];
                int k = kb + q * 4;
                Xs[(k + 0) * MTILE + ms] = v.x;
                Xs[(k + 1) * MTILE + ms] = v.y;
                Xs[(k + 2) * MTILE + ms] = v.z;
                Xs[(k + 3) * MTILE + ms] = v.w;
            }
        } else {
            #pragma unroll
            for (int q = 0; q < 8; q++) {
                int k = kb + q * 4;
                Xs[(k + 0) * MTILE + ms] = 0.f;
                Xs[(k + 1) * MTILE + ms] = 0.f;
                Xs[(k + 2) * MTILE + ms] = 0.f;
                Xs[(k + 3) * MTILE + ms] = 0.f;
            }
        }
    }
    __syncthreads();

    // compute: 16(n) x 16(m) threads, 4m x 8n micro-tile, k stepped by 2.
    // acc lanes: .lo = even-k partial, .hi = odd-k partial.
    const int tx = tid & 15;
    const int ty = tid >> 4;
    const int n0 = tx * 8;
    const int m0 = ty * 4;

    ull acc[4][8];
    #pragma unroll
    for (int i = 0; i < 4; i++)
        #pragma unroll
        for (int j = 0; j < 8; j++) acc[i][j] = 0ULL;

    #pragma unroll 2
    for (int k = 0; k < D; k += 2) {
        const int msw = m0 ^ (((k >> 5) & 3) << 3);
        float4 xa = *(const float4*)&Xs[ k      * MTILE + msw];
        float4 xb = *(const float4*)&Xs[(k + 1) * MTILE + msw];
        ull xm[4];
        xm[0] = pk(xa.x, xb.x); xm[1] = pk(xa.y, xb.y);
        xm[2] = pk(xa.z, xb.z); xm[3] = pk(xa.w, xb.w);

        float4 wa0 = *(const float4*)&Ws[ k      * D + n0];
        float4 wa1 = *(const float4*)&Ws[ k      * D + n0 + 4];
        float4 wb0 = *(const float4*)&Ws[(k + 1) * D + n0];
        float4 wb1 = *(const float4*)&Ws[(k + 1) * D + n0 + 4];
        ull wn[8];
        wn[0] = pk(wa0.x, wb0.x); wn[1] = pk(wa0.y, wb0.y);
        wn[2] = pk(wa0.z, wb0.z); wn[3] = pk(wa0.w, wb0.w);
        wn[4] = pk(wa1.x, wb1.x); wn[5] = pk(wa1.y, wb1.y);
        wn[6] = pk(wa1.z, wb1.z); wn[7] = pk(wa1.w, wb1.w);

        #pragma unroll
        for (int i = 0; i < 4; i++)
            #pragma unroll
            for (int j = 0; j < 8; j++)
                acc[i][j] = ffma2(xm[i], wn[j], acc[i][j]);
    }

    // bias + horizontal add + store
    float4 b0 = *(const float4*)&Bv[e * D + n0];
    float4 b1 = *(const float4*)&Bv[e * D + n0 + 4];
    const float bb[8] = {b0.x, b0.y, b0.z, b0.w, b1.x, b1.y, b1.z, b1.w};

    #pragma unroll
    for (int i = 0; i < 4; i++) {
        int m = m0 + i;
        if (m < mvalid) {
            int t = idxs[m];
            float* yr = Y + (size_t)t * D + n0;
            float4 o0, o1;
            float2 v;
            v = unpk(acc[i][0]); o0.x = v.x + v.y + bb[0];
            v = unpk(acc[i][1]); o0.y = v.x + v.y + bb[1];
            v = unpk(acc[i][2]); o0.z = v.x + v.y + bb[2];
            v = unpk(acc[i][3]); o0.w = v.x + v.y + bb[3];
            v = unpk(acc[i][4]); o1.x = v.x + v.y + bb[4];
            v = unpk(acc[i][5]); o1.y = v.x + v.y + bb[5];
            v = unpk(acc[i][6]); o1.z = v.x + v.y + bb[6];
            v = unpk(acc[i][7]); o1.w = v.x + v.y + bb[7];
            *(float4*)(yr)     = o0;
            *(float4*)(yr + 4) = o1;
        }
    }
}

static const int GEMM_SMEM = (D * D + D * MTILE) * 4 + MTILE * 4;  // 98560 B

extern "C" void kernel_launch(void* const* d_in, const int* in_sizes, int n_in,
                              void* d_out, int out_size) {
    const int*   positions = (const int*)d_in[0];
    const float* X  = (const float*)d_in[1];
    const float* W  = (const float*)d_in[2];
    const float* Bv = (const float*)d_in[3];
    float* Y = (float*)d_out;

    cudaFuncSetAttribute(gemm_kernel,
                         cudaFuncAttributeMaxDynamicSharedMemorySize, GEMM_SMEM);

    bucket_kernel<<<1, BT>>>(positions);
    dim3 grid(NEXP, (NTOK + MTILE - 1) / MTILE);
    gemm_kernel<<<grid, 256, GEMM_SMEM>>>(X, W, Bv, Y);
}

// round 9
// speedup vs baseline: 1.1972x; 1.1972x over previous
#include <cuda_runtime.h>
#include <cstdint>

#define NTOK   8192
#define D      128
#define NEXP   9
#define MT     128
#define BT     256
#define XSTR   132          // padded f32 stride (bank-conflict-free fragments)

__device__ int g_counts[NEXP];
__device__ int g_buckets[NEXP * NTOK];

// ---------------- bucketing: register counts + shuffle scan, deterministic ----
__global__ __launch_bounds__(BT) void bucket_kernel(const int* __restrict__ positions) {
    const int t = threadIdx.x, lane = t & 31, wid = t >> 5;
    __shared__ int wtot[NEXP][8];
    __shared__ int wbase[NEXP][8];

    int cnt[NEXP];
    #pragma unroll
    for (int e = 0; e < NEXP; e++) cnt[e] = 0;

    const int base = t * 32;
    #pragma unroll 8
    for (int i = 0; i < 32; i++) {
        int r = min(max(positions[base + i], 0), NEXP - 1);
        cnt[r]++;
    }

    int excl[NEXP];
    #pragma unroll
    for (int e = 0; e < NEXP; e++) {
        int v = cnt[e], s = v;
        #pragma unroll
        for (int off = 1; off < 32; off <<= 1) {
            int u = __shfl_up_sync(0xFFFFFFFFu, s, off);
            if (lane >= off) s += u;
        }
        excl[e] = s - v;
        if (lane == 31) wtot[e][wid] = s;
    }
    __syncthreads();
    if (t < NEXP) {
        int run = 0;
        #pragma unroll
        for (int w = 0; w < 8; w++) { wbase[t][w] = run; run += wtot[t][w]; }
        g_counts[t] = run;
    }
    __syncthreads();

    int off[NEXP];
    #pragma unroll
    for (int e = 0; e < NEXP; e++) off[e] = wbase[e][wid] + excl[e];

    #pragma unroll 8
    for (int i = 0; i < 32; i++) {
        int tok = base + i;
        int r = min(max(positions[tok], 0), NEXP - 1);
        g_buckets[r * NTOK + off[r]++] = tok;
    }
}

// ---------------- tf32 helpers ----------------
__device__ __forceinline__ uint32_t f2tf(float x) {
    uint32_t r; asm("cvt.rna.tf32.f32 %0, %1;" : "=r"(r) : "f"(x)); return r;
}
__device__ __forceinline__ void mma8(float* d, const uint32_t* a, uint32_t b0, uint32_t b1) {
    asm volatile(
        "mma.sync.aligned.m16n8k8.row.col.f32.tf32.tf32.f32 "
        "{%0,%1,%2,%3}, {%4,%5,%6,%7}, {%8,%9}, {%0,%1,%2,%3};"
        : "+f"(d[0]), "+f"(d[1]), "+f"(d[2]), "+f"(d[3])
        : "r"(a[0]), "r"(a[1]), "r"(a[2]), "r"(a[3]), "r"(b0), "r"(b1));
}

// ---------------- grouped GEMM: 3xTF32 mma.sync -------------------------------
// Y[m][n] = sum_k X[m][k]*W[e][k][n] + b[e][n]; Xs[m][k], Bs[n][k] (=W^T), pad 132.
__global__ __launch_bounds__(256) void gemm_kernel(
    const float* __restrict__ X, const float* __restrict__ W,
    const float* __restrict__ Bv, float* __restrict__ Y)
{
    extern __shared__ float smem[];
    float* Xs = smem;                        // 128*132
    float* Bs = smem + D * XSTR;             // 128*132
    int*   idxs = (int*)(smem + 2 * D * XSTR);      // 128
    float* sB   = (float*)(idxs + D);               // 128

    const int e     = blockIdx.x;
    const int count = g_counts[e];
    const int m0g   = blockIdx.y * MT;
    if (m0g >= count) return;
    const int mvalid = min(MT, count - m0g);

    const int tid = threadIdx.x, lane = tid & 31, wid = tid >> 5;

    if (tid < D)
        idxs[tid] = (tid < mvalid) ? g_buckets[e * NTOK + m0g + tid] : -1;
    if (tid >= 224)
        ((float4*)sB)[tid - 224] = ((const float4*)(Bv + e * D))[tid - 224];
    __syncthreads();

    // stage X rows (2 threads per row, 16 float4 each); zero-fill invalid rows
    {
        const int m = tid >> 1, half = tid & 1;
        const int tok = idxs[m];
        float4* dst = (float4*)&Xs[m * XSTR + half * 64];
        if (tok >= 0) {
            const float4* xr = (const float4*)(X + (size_t)tok * D + half * 64);
            #pragma unroll
            for (int q = 0; q < 16; q++) dst[q] = xr[q];
        } else {
            const float4 z = {0.f, 0.f, 0.f, 0.f};
            #pragma unroll
            for (int q = 0; q < 16; q++) dst[q] = z;
        }
    }
    // stage W^T: Bs[n][k] = W[e][k][n]
    {
        const float4* Wg = (const float4*)(W + (size_t)e * D * D);
        #pragma unroll
        for (int i = 0; i < 16; i++) {
            int q = tid + i * 256;
            int k = q >> 5, n4 = (q & 31) * 4;
            float4 v = Wg[q];
            Bs[(n4 + 0) * XSTR + k] = v.x;
            Bs[(n4 + 1) * XSTR + k] = v.y;
            Bs[(n4 + 2) * XSTR + k] = v.z;
            Bs[(n4 + 3) * XSTR + k] = v.w;
        }
    }
    __syncthreads();

    // warp tiling: 4 m-warps x 2 n-warps; warp tile 32(m) x 64(n)
    const int wm = (wid & 3) * 32;
    const int wn = (wid >> 2) * 64;
    const int g = lane >> 2, c = lane & 3;

    float acc[2][8][4];
    #pragma unroll
    for (int mt = 0; mt < 2; mt++)
        #pragma unroll
        for (int nt = 0; nt < 8; nt++)
            #pragma unroll
            for (int j = 0; j < 4; j++) acc[mt][nt][j] = 0.f;

    #pragma unroll 4
    for (int kk = 0; kk < 16; kk++) {
        const int k0 = kk * 8;
        uint32_t ah[2][4], al[2][4];
        #pragma unroll
        for (int mt = 0; mt < 2; mt++) {
            const float* xr0 = &Xs[(wm + mt * 16 + g) * XSTR + k0];
            const float* xr1 = xr0 + 8 * XSTR;
            float f[4] = {xr0[c], xr1[c], xr0[c + 4], xr1[c + 4]};
            #pragma unroll
            for (int j = 0; j < 4; j++) {
                ah[mt][j] = f2tf(f[j]);
                al[mt][j] = f2tf(f[j] - __uint_as_float(ah[mt][j]));
            }
        }
        #pragma unroll
        for (int nt = 0; nt < 8; nt++) {
            const float* br = &Bs[(wn + nt * 8 + g) * XSTR + k0];
            float b0f = br[c], b1f = br[c + 4];
            uint32_t bh0 = f2tf(b0f), bh1 = f2tf(b1f);
            uint32_t bl0 = f2tf(b0f - __uint_as_float(bh0));
            uint32_t bl1 = f2tf(b1f - __uint_as_float(bh1));
            #pragma unroll
            for (int mt = 0; mt < 2; mt++) {
                mma8(acc[mt][nt], ah[mt], bh0, bh1);   // hh
                mma8(acc[mt][nt], ah[mt], bl0, bl1);   // hl
                mma8(acc[mt][nt], al[mt], bh0, bh1);   // lh
            }
        }
    }

    // epilogue: fragment rows g, g+8; cols 2c, 2c+1 per 8-wide n tile
    #pragma unroll
    for (int mt = 0; mt < 2; mt++) {
        #pragma unroll
        for (int rp = 0; rp < 2; rp++) {
            const int row = wm + mt * 16 + g + rp * 8;
            const int tok = idxs[row];
            if (tok < 0) continue;
            float* yr = Y + (size_t)tok * D;
            #pragma unroll
            for (int nt = 0; nt < 8; nt++) {
                const int col = wn + nt * 8 + 2 * c;
                float2 o;
                o.x = acc[mt][nt][rp * 2 + 0] + sB[col];
                o.y = acc[mt][nt][rp * 2 + 1] + sB[col + 1];
                *(float2*)(yr + col) = o;
            }
        }
    }
}

static const int GEMM_SMEM = (2 * D * XSTR + D + D) * 4;   // ~136 KB

extern "C" void kernel_launch(void* const* d_in, const int* in_sizes, int n_in,
                              void* d_out, int out_size) {
    const int*   positions = (const int*)d_in[0];
    const float* X  = (const float*)d_in[1];
    const float* W  = (const float*)d_in[2];
    const float* Bv = (const float*)d_in[3];
    float* Y = (float*)d_out;

    cudaFuncSetAttribute(gemm_kernel,
                         cudaFuncAttributeMaxDynamicSharedMemorySize, GEMM_SMEM);

    bucket_kernel<<<1, BT>>>(positions);
    dim3 grid(NEXP, NTOK / MT);
    gemm_kernel<<<grid, 256, GEMM_SMEM>>>(X, W, Bv, Y);
}

// round 11
// speedup vs baseline: 1.8889x; 1.5778x over previous
#include <cuda_runtime.h>
#include <cstdint>

#define NTOK   8192
#define D      128
#define NEXP   9
#define MT     128
#define NT_THREADS 512
#define XSTR   132

// ---------------- tf32 helpers ----------------
__device__ __forceinline__ uint32_t f2tf(float x) {
    uint32_t r; asm("cvt.rna.tf32.f32 %0, %1;" : "=r"(r) : "f"(x)); return r;
}
__device__ __forceinline__ void mma8(float* d, const uint32_t* a, uint32_t b0, uint32_t b1) {
    asm volatile(
        "mma.sync.aligned.m16n8k8.row.col.f32.tf32.tf32.f32 "
        "{%0,%1,%2,%3}, {%4,%5,%6,%7}, {%8,%9}, {%0,%1,%2,%3};"
        : "+f"(d[0]), "+f"(d[1]), "+f"(d[2]), "+f"(d[3])
        : "r"(a[0]), "r"(a[1]), "r"(a[2]), "r"(a[3]), "r"(b0), "r"(b1));
}

// One fused kernel: block (e, tile) self-computes its token list (stable scan),
// stages X and W^T, runs 3xTF32 mma.sync, writes Y. Stateless & deterministic.
__global__ __launch_bounds__(NT_THREADS) void fused_kernel(
    const int*   __restrict__ positions,
    const float* __restrict__ X, const float* __restrict__ W,
    const float* __restrict__ Bv, float* __restrict__ Y)
{
    extern __shared__ float smem[];
    float* Xs  = smem;                               // 128*132
    float* Bs  = smem + D * XSTR;                    // 128*132
    int*   idxs = (int*)(smem + 2 * D * XSTR);       // 128
    float* sB   = (float*)(idxs + MT);               // 128
    int*   wtot = (int*)(sB + D);                    // 16
    int*   wbase = wtot + 16;                        // 16
    int*   stot  = wbase + 16;                       // 1

    const int e   = blockIdx.x;
    const int m0g = blockIdx.y * MT;
    const int tid = threadIdx.x, lane = tid & 31, wid = tid >> 5;

    // ---- phase 1: membership bitmask over my 16 tokens ----
    uint32_t mask = 0;
    {
        const int4* pp = (const int4*)(positions + tid * 16);
        #pragma unroll
        for (int q = 0; q < 4; q++) {
            int4 v = pp[q];
            int rr[4] = {v.x, v.y, v.z, v.w};
            #pragma unroll
            for (int j = 0; j < 4; j++) {
                int r = min(max(rr[j], 0), NEXP - 1);
                if (r == e) mask |= 1u << (q * 4 + j);
            }
        }
    }
    const int c = __popc(mask);
    int s = c;
    #pragma unroll
    for (int off = 1; off < 32; off <<= 1) {
        int u = __shfl_up_sync(0xFFFFFFFFu, s, off);
        if (lane >= off) s += u;
    }
    if (lane == 31) wtot[wid] = s;
    __syncthreads();
    if (tid == 0) {
        int run = 0;
        #pragma unroll
        for (int w = 0; w < 16; w++) { wbase[w] = run; run += wtot[w]; }
        stot[0] = run;
    }
    __syncthreads();
    const int count = stot[0];
    if (m0g >= count) return;                 // whole block agrees -> safe exit

    // ---- phase 2: stable collect of ranks within [m0g, m0g+MT) ----
    if (tid < MT) idxs[tid] = -1;
    if (tid >= NT_THREADS - 32)
        ((float4*)sB)[tid - (NT_THREADS - 32)] =
            ((const float4*)(Bv + e * D))[tid - (NT_THREADS - 32)];
    __syncthreads();
    {
        int rank = wbase[wid] + (s - c);
        #pragma unroll
        for (int i = 0; i < 16; i++) {
            if ((mask >> i) & 1u) {
                int rel = rank - m0g;
                if (rel >= 0 && rel < MT) idxs[rel] = tid * 16 + i;
                rank++;
            }
        }
    }
    __syncthreads();

    // ---- stage X rows (4 threads per row) ----
    {
        const int m = tid >> 2, qtr = tid & 3;
        const int tok = idxs[m];
        float4* dst = (float4*)&Xs[m * XSTR + qtr * 32];
        if (tok >= 0) {
            const float4* xr = (const float4*)(X + (size_t)tok * D + qtr * 32);
            #pragma unroll
            for (int q = 0; q < 8; q++) dst[q] = xr[q];
        } else {
            const float4 z = {0.f, 0.f, 0.f, 0.f};
            #pragma unroll
            for (int q = 0; q < 8; q++) dst[q] = z;
        }
    }
    // ---- stage W^T: Bs[n][k] = W[e][k][n] ----
    {
        const float4* Wg = (const float4*)(W + (size_t)e * D * D);
        #pragma unroll
        for (int i = 0; i < 8; i++) {
            int q = tid + i * NT_THREADS;
            int k = q >> 5, n4 = (q & 31) * 4;
            float4 v = Wg[q];
            Bs[(n4 + 0) * XSTR + k] = v.x;
            Bs[(n4 + 1) * XSTR + k] = v.y;
            Bs[(n4 + 2) * XSTR + k] = v.z;
            Bs[(n4 + 3) * XSTR + k] = v.w;
        }
    }
    __syncthreads();

    // ---- mainloop: 4m x 4n warps, warp tile 32x32, 3xTF32 ----
    const int wm = (wid & 3) * 32;
    const int wn = (wid >> 2) * 32;
    const int g = lane >> 2, cq = lane & 3;

    float acc[2][4][4];
    #pragma unroll
    for (int mt = 0; mt < 2; mt++)
        #pragma unroll
        for (int nt = 0; nt < 4; nt++)
            #pragma unroll
            for (int j = 0; j < 4; j++) acc[mt][nt][j] = 0.f;

    #pragma unroll 4
    for (int kk = 0; kk < 16; kk++) {
        const int k0 = kk * 8;
        uint32_t ah[2][4], al[2][4];
        #pragma unroll
        for (int mt = 0; mt < 2; mt++) {
            const float* xr0 = &Xs[(wm + mt * 16 + g) * XSTR + k0];
            const float* xr1 = xr0 + 8 * XSTR;
            float f[4] = {xr0[cq], xr1[cq], xr0[cq + 4], xr1[cq + 4]};
            #pragma unroll
            for (int j = 0; j < 4; j++) {
                ah[mt][j] = f2tf(f[j]);
                al[mt][j] = f2tf(f[j] - __uint_as_float(ah[mt][j]));
            }
        }
        #pragma unroll
        for (int nt = 0; nt < 4; nt++) {
            const float* br = &Bs[(wn + nt * 8 + g) * XSTR + k0];
            float b0f = br[cq], b1f = br[cq + 4];
            uint32_t bh0 = f2tf(b0f), bh1 = f2tf(b1f);
            uint32_t bl0 = f2tf(b0f - __uint_as_float(bh0));
            uint32_t bl1 = f2tf(b1f - __uint_as_float(bh1));
            #pragma unroll
            for (int mt = 0; mt < 2; mt++) {
                mma8(acc[mt][nt], ah[mt], bh0, bh1);   // hh
                mma8(acc[mt][nt], ah[mt], bl0, bl1);   // hl
                mma8(acc[mt][nt], al[mt], bh0, bh1);   // lh
            }
        }
    }

    // ---- epilogue ----
    #pragma unroll
    for (int mt = 0; mt < 2; mt++) {
        #pragma unroll
        for (int rp = 0; rp < 2; rp++) {
            const int row = wm + mt * 16 + g + rp * 8;
            const int tok = idxs[row];
            if (tok < 0) continue;
            float* yr = Y + (size_t)tok * D;
            #pragma unroll
            for (int nt = 0; nt < 4; nt++) {
                const int col = wn + nt * 8 + 2 * cq;
                float2 o;
                o.x = acc[mt][nt][rp * 2 + 0] + sB[col];
                o.y = acc[mt][nt][rp * 2 + 1] + sB[col + 1];
                *(float2*)(yr + col) = o;
            }
        }
    }
}

static const int FUSED_SMEM = (2 * D * XSTR + MT + D + 33) * 4;  // ~136 KB

extern "C" void kernel_launch(void* const* d_in, const int* in_sizes, int n_in,
                              void* d_out, int out_size) {
    const int*   positions = (const int*)d_in[0];
    const float* X  = (const float*)d_in[1];
    const float* W  = (const float*)d_in[2];
    const float* Bv = (const float*)d_in[3];
    float* Y = (float*)d_out;

    cudaFuncSetAttribute(fused_kernel,
                         cudaFuncAttributeMaxDynamicSharedMemorySize, FUSED_SMEM);

    dim3 grid(NEXP, NTOK / MT);
    fused_kernel<<<grid, NT_THREADS, FUSED_SMEM>>>(positions, X, W, Bv, Y);
}

// round 12
// speedup vs baseline: 1.9388x; 1.0264x over previous
#include <cuda_runtime.h>
#include <cuda_bf16.h>
#include <cstdint>

#define NTOK   8192
#define D      128
#define NEXP   9
#define MT     128
#define NT_THREADS 512

// byte offsets in dynamic smem
#define SM_AH   0
#define SM_AL   32768
#define SM_BH   65536
#define SM_BL   98304
#define SM_IDX  131072              // 128 int
#define SM_BIAS 131584              // 128 f32
#define SM_SCAN 132096              // 33 int
#define SM_TOT  132352

// row = 256 bytes (128 bf16) = 64 u32 words; swizzle word index by row
__device__ __forceinline__ int swz(int kw, int row) {
    return kw ^ ((row & 15) << 2);
}

__device__ __forceinline__ uint32_t pack_bf2(__nv_bfloat16 a, __nv_bfloat16 b) {
    __nv_bfloat162 t; t.x = a; t.y = b;
    return *(uint32_t*)&t;
}
// split v into hi/lo bf16
__device__ __forceinline__ void split(float v, __nv_bfloat16& h, __nv_bfloat16& l) {
    h = __float2bfloat16(v);
    l = __float2bfloat16(v - __bfloat162float(h));
}

__device__ __forceinline__ void mma16(float* d, const uint32_t* a, uint32_t b0, uint32_t b1) {
    asm volatile(
        "mma.sync.aligned.m16n8k16.row.col.f32.bf16.bf16.f32 "
        "{%0,%1,%2,%3}, {%4,%5,%6,%7}, {%8,%9}, {%0,%1,%2,%3};"
        : "+f"(d[0]), "+f"(d[1]), "+f"(d[2]), "+f"(d[3])
        : "r"(a[0]), "r"(a[1]), "r"(a[2]), "r"(a[3]), "r"(b0), "r"(b1));
}

__global__ __launch_bounds__(NT_THREADS) void fused_kernel(
    const int*   __restrict__ positions,
    const float* __restrict__ X, const float* __restrict__ W,
    const float* __restrict__ Bv, float* __restrict__ Y)
{
    extern __shared__ char smem[];
    uint32_t* Ah = (uint32_t*)(smem + SM_AH);   // [128 rows][64 words], swizzled
    uint32_t* Al = (uint32_t*)(smem + SM_AL);
    uint32_t* Bh = (uint32_t*)(smem + SM_BH);
    uint32_t* Bl = (uint32_t*)(smem + SM_BL);
    int*   idxs = (int*)(smem + SM_IDX);
    float* sB   = (float*)(smem + SM_BIAS);
    int*   wtot = (int*)(smem + SM_SCAN);       // 16
    int*   wbase = wtot + 16;                   // 16
    int*   stot  = wbase + 16;                  // 1

    const int e   = blockIdx.x;
    const int m0g = blockIdx.y * MT;
    const int tid = threadIdx.x, lane = tid & 31, wid = tid >> 5;

    // ---- phase 1: membership scan (as round 11) ----
    uint32_t mask = 0;
    {
        const int4* pp = (const int4*)(positions + tid * 16);
        #pragma unroll
        for (int q = 0; q < 4; q++) {
            int4 v = pp[q];
            int rr[4] = {v.x, v.y, v.z, v.w};
            #pragma unroll
            for (int j = 0; j < 4; j++) {
                int r = min(max(rr[j], 0), NEXP - 1);
                if (r == e) mask |= 1u << (q * 4 + j);
            }
        }
    }
    const int c = __popc(mask);
    int s = c;
    #pragma unroll
    for (int off = 1; off < 32; off <<= 1) {
        int u = __shfl_up_sync(0xFFFFFFFFu, s, off);
        if (lane >= off) s += u;
    }
    if (lane == 31) wtot[wid] = s;
    __syncthreads();
    if (tid == 0) {
        int run = 0;
        #pragma unroll
        for (int w = 0; w < 16; w++) { wbase[w] = run; run += wtot[w]; }
        stot[0] = run;
    }
    __syncthreads();
    const int count = stot[0];
    if (m0g >= count) return;

    // ---- phase 2: stable collect into window ----
    if (tid < MT) idxs[tid] = -1;
    if (tid >= NT_THREADS - 32)
        ((float4*)sB)[tid - (NT_THREADS - 32)] =
            ((const float4*)(Bv + e * D))[tid - (NT_THREADS - 32)];
    __syncthreads();
    {
        int rank = wbase[wid] + (s - c);
        #pragma unroll
        for (int i = 0; i < 16; i++) {
            if ((mask >> i) & 1u) {
                int rel = rank - m0g;
                if (rel >= 0 && rel < MT) idxs[rel] = tid * 16 + i;
                rank++;
            }
        }
    }
    __syncthreads();

    // ---- stage X -> Ah/Al (4 threads per row, split to bf16 hi/lo) ----
    {
        const int m = tid >> 2, qtr = tid & 3;
        const int tok = idxs[m];
        uint32_t* ah = Ah + m * 64;
        uint32_t* al = Al + m * 64;
        if (tok >= 0) {
            const float4* xr = (const float4*)(X + (size_t)tok * D + qtr * 32);
            #pragma unroll
            for (int q = 0; q < 8; q++) {
                float4 v = xr[q];
                __nv_bfloat16 h0, h1, h2, h3, l0, l1, l2, l3;
                split(v.x, h0, l0); split(v.y, h1, l1);
                split(v.z, h2, l2); split(v.w, h3, l3);
                int kw = qtr * 16 + q * 2;
                ah[swz(kw, m)]     = pack_bf2(h0, h1);
                ah[swz(kw + 1, m)] = pack_bf2(h2, h3);
                al[swz(kw, m)]     = pack_bf2(l0, l1);
                al[swz(kw + 1, m)] = pack_bf2(l2, l3);
            }
        } else {
            #pragma unroll
            for (int q = 0; q < 8; q++) {
                int kw = qtr * 16 + q * 2;
                ah[swz(kw, m)] = 0;  ah[swz(kw + 1, m)] = 0;
                al[swz(kw, m)] = 0;  al[swz(kw + 1, m)] = 0;
            }
        }
    }
    // ---- stage W^T -> Bh/Bl: thread owns column n, k-range of 32 ----
    {
        const int n  = tid & 127;
        const int kq = (tid >> 7) * 32;
        const float* wp = W + (size_t)e * D * D + (size_t)kq * D + n;
        uint32_t* bh = Bh + n * 64;
        uint32_t* bl = Bl + n * 64;
        #pragma unroll
        for (int kk = 0; kk < 16; kk++) {
            float v0 = wp[(2 * kk) * D];
            float v1 = wp[(2 * kk + 1) * D];
            __nv_bfloat16 h0, h1, l0, l1;
            split(v0, h0, l0); split(v1, h1, l1);
            int kw = kq / 2 + kk;
            bh[swz(kw, n)] = pack_bf2(h0, h1);
            bl[swz(kw, n)] = pack_bf2(l0, l1);
        }
    }
    __syncthreads();

    // ---- mainloop: 4m x 4n warps, warp tile 32x32, bf16 k16, 3 passes ----
    const int wm = (wid & 3) * 32;
    const int wn = (wid >> 2) * 32;
    const int g = lane >> 2, cq = lane & 3;

    float acc[2][4][4];
    #pragma unroll
    for (int mt = 0; mt < 2; mt++)
        #pragma unroll
        for (int nt = 0; nt < 4; nt++)
            #pragma unroll
            for (int j = 0; j < 4; j++) acc[mt][nt][j] = 0.f;

    #pragma unroll 4
    for (int ks = 0; ks < 8; ks++) {
        const int k0w = ks * 8;
        uint32_t ah[2][4], al[2][4], bh[4][2], bl[4][2];
        #pragma unroll
        for (int mt = 0; mt < 2; mt++) {
            const int r0 = wm + mt * 16 + g;
            const int r1 = r0 + 8;
            const uint32_t* a0 = Ah + r0 * 64;
            const uint32_t* a1 = Ah + r1 * 64;
            const uint32_t* c0 = Al + r0 * 64;
            const uint32_t* c1 = Al + r1 * 64;
            ah[mt][0] = a0[swz(k0w + cq, r0)];
            ah[mt][1] = a1[swz(k0w + cq, r1)];
            ah[mt][2] = a0[swz(k0w + cq + 4, r0)];
            ah[mt][3] = a1[swz(k0w + cq + 4, r1)];
            al[mt][0] = c0[swz(k0w + cq, r0)];
            al[mt][1] = c1[swz(k0w + cq, r1)];
            al[mt][2] = c0[swz(k0w + cq + 4, r0)];
            al[mt][3] = c1[swz(k0w + cq + 4, r1)];
        }
        #pragma unroll
        for (int nt = 0; nt < 4; nt++) {
            const int n = wn + nt * 8 + g;
            const uint32_t* b0 = Bh + n * 64;
            const uint32_t* b1 = Bl + n * 64;
            bh[nt][0] = b0[swz(k0w + cq, n)];
            bh[nt][1] = b0[swz(k0w + cq + 4, n)];
            bl[nt][0] = b1[swz(k0w + cq, n)];
            bl[nt][1] = b1[swz(k0w + cq + 4, n)];
        }
        // pass-major order: each acc touched once per 8 MMAs
        #pragma unroll
        for (int nt = 0; nt < 4; nt++)
            #pragma unroll
            for (int mt = 0; mt < 2; mt++)
                mma16(acc[mt][nt], ah[mt], bh[nt][0], bh[nt][1]);   // hh
        #pragma unroll
        for (int nt = 0; nt < 4; nt++)
            #pragma unroll
            for (int mt = 0; mt < 2; mt++)
                mma16(acc[mt][nt], ah[mt], bl[nt][0], bl[nt][1]);   // hl
        #pragma unroll
        for (int nt = 0; nt < 4; nt++)
            #pragma unroll
            for (int mt = 0; mt < 2; mt++)
                mma16(acc[mt][nt], al[mt], bh[nt][0], bh[nt][1]);   // lh
    }

    // ---- epilogue ----
    #pragma unroll
    for (int mt = 0; mt < 2; mt++) {
        #pragma unroll
        for (int rp = 0; rp < 2; rp++) {
            const int row = wm + mt * 16 + g + rp * 8;
            const int tok = idxs[row];
            if (tok < 0) continue;
            float* yr = Y + (size_t)tok * D;
            #pragma unroll
            for (int nt = 0; nt < 4; nt++) {
                const int col = wn + nt * 8 + 2 * cq;
                float2 o;
                o.x = acc[mt][nt][rp * 2 + 0] + sB[col];
                o.y = acc[mt][nt][rp * 2 + 1] + sB[col + 1];
                *(float2*)(yr + col) = o;
            }
        }
    }
}

extern "C" void kernel_launch(void* const* d_in, const int* in_sizes, int n_in,
                              void* d_out, int out_size) {
    const int*   positions = (const int*)d_in[0];
    const float* X  = (const float*)d_in[1];
    const float* W  = (const float*)d_in[2];
    const float* Bv = (const float*)d_in[3];
    float* Y = (float*)d_out;

    cudaFuncSetAttribute(fused_kernel,
                         cudaFuncAttributeMaxDynamicSharedMemorySize, SM_TOT);

    dim3 grid(NEXP, NTOK / MT);
    fused_kernel<<<grid, NT_THREADS, SM_TOT>>>(positions, X, W, Bv, Y);
}

// round 14
// speedup vs baseline: 2.7327x; 1.4095x over previous
#include <cuda_runtime.h>
#include <cuda_bf16.h>
#include <cstdint>

#define NTOK   8192
#define D      128
#define NEXP   9
#define MT     64
#define NT_THREADS 512

// byte offsets in dynamic smem (row = 64 u32 words = 128 bf16 = 256B)
#define SM_AH   0                    // 64 * 256
#define SM_AL   16384
#define SM_BH   32768                // 128 * 256
#define SM_BL   65536
#define SM_IDX  98304                // 64 int
#define SM_BIAS 98560                // 128 f32
#define SM_SCAN 99072                // 33 int
#define SM_TOT  99328

__device__ __forceinline__ int swz(int kw, int row) {
    return kw ^ ((row & 15) << 2);
}
__device__ __forceinline__ uint32_t pack_bf2(__nv_bfloat16 a, __nv_bfloat16 b) {
    __nv_bfloat162 t; t.x = a; t.y = b;
    return *(uint32_t*)&t;
}
__device__ __forceinline__ void split(float v, __nv_bfloat16& h, __nv_bfloat16& l) {
    h = __float2bfloat16(v);
    l = __float2bfloat16(v - __bfloat162float(h));
}
__device__ __forceinline__ void mma16(float* d, const uint32_t* a, uint32_t b0, uint32_t b1) {
    asm volatile(
        "mma.sync.aligned.m16n8k16.row.col.f32.bf16.bf16.f32 "
        "{%0,%1,%2,%3}, {%4,%5,%6,%7}, {%8,%9}, {%0,%1,%2,%3};"
        : "+f"(d[0]), "+f"(d[1]), "+f"(d[2]), "+f"(d[3])
        : "r"(a[0]), "r"(a[1]), "r"(a[2]), "r"(a[3]), "r"(b0), "r"(b1));
}
__device__ __forceinline__ void ldsm4(uint32_t* r, uint32_t addr) {
    asm volatile("ldmatrix.sync.aligned.m8n8.x4.shared.b16 {%0,%1,%2,%3}, [%4];"
        : "=r"(r[0]), "=r"(r[1]), "=r"(r[2]), "=r"(r[3]) : "r"(addr));
}
__device__ __forceinline__ uint32_t smem_u32(const void* p) {
    uint32_t a;
    asm("{ .reg .u64 t; cvta.to.shared.u64 t, %1; cvt.u32.u64 %0, t; }" : "=r"(a) : "l"(p));
    return a;
}

__global__ __launch_bounds__(NT_THREADS, 2) void fused_kernel(
    const int*   __restrict__ positions,
    const float* __restrict__ X, const float* __restrict__ W,
    const float* __restrict__ Bv, float* __restrict__ Y)
{
    extern __shared__ char smem[];
    const uint32_t sb = smem_u32(smem);
    uint32_t* Ah = (uint32_t*)(smem + SM_AH);
    uint32_t* Al = (uint32_t*)(smem + SM_AL);
    uint32_t* Bh = (uint32_t*)(smem + SM_BH);
    uint32_t* Bl = (uint32_t*)(smem + SM_BL);
    int*   idxs = (int*)(smem + SM_IDX);
    float* sB   = (float*)(smem + SM_BIAS);
    int*   wtot = (int*)(smem + SM_SCAN);
    int*   wbase = wtot + 16;
    int*   stot  = wbase + 16;

    const int e   = blockIdx.x;
    const int m0g = blockIdx.y * MT;
    const int tid = threadIdx.x, lane = tid & 31, wid = tid >> 5;

    // ---- phase 1: membership scan ----
    uint32_t mask = 0;
    {
        const int4* pp = (const int4*)(positions + tid * 16);
        #pragma unroll
        for (int q = 0; q < 4; q++) {
            int4 v = pp[q];
            int rr[4] = {v.x, v.y, v.z, v.w};
            #pragma unroll
            for (int j = 0; j < 4; j++) {
                int r = min(max(rr[j], 0), NEXP - 1);
                if (r == e) mask |= 1u << (q * 4 + j);
            }
        }
    }
    const int c = __popc(mask);
    int s = c;
    #pragma unroll
    for (int off = 1; off < 32; off <<= 1) {
        int u = __shfl_up_sync(0xFFFFFFFFu, s, off);
        if (lane >= off) s += u;
    }
    if (lane == 31) wtot[wid] = s;
    __syncthreads();
    if (tid == 0) {
        int run = 0;
        #pragma unroll
        for (int w = 0; w < 16; w++) { wbase[w] = run; run += wtot[w]; }
        stot[0] = run;
    }
    __syncthreads();
    const int count = stot[0];
    if (m0g >= count) return;

    // ---- phase 2: stable collect into window ----
    if (tid < MT) idxs[tid] = -1;
    if (tid >= NT_THREADS - 32)
        ((float4*)sB)[tid - (NT_THREADS - 32)] =
            ((const float4*)(Bv + e * D))[tid - (NT_THREADS - 32)];
    __syncthreads();
    {
        int rank = wbase[wid] + (s - c);
        #pragma unroll
        for (int i = 0; i < 16; i++) {
            if ((mask >> i) & 1u) {
                int rel = rank - m0g;
                if (rel >= 0 && rel < MT) idxs[rel] = tid * 16 + i;
                rank++;
            }
        }
    }
    __syncthreads();

    // ---- stage X -> Ah/Al (8 threads per row; 16 floats each) ----
    {
        const int m = tid >> 3, o = tid & 7;
        const int tok = idxs[m];
        uint32_t* ah = Ah + m * 64;
        uint32_t* al = Al + m * 64;
        if (tok >= 0) {
            const float4* xr = (const float4*)(X + (size_t)tok * D + o * 16);
            #pragma unroll
            for (int q = 0; q < 4; q++) {
                float4 v = xr[q];
                __nv_bfloat16 h0, h1, h2, h3, l0, l1, l2, l3;
                split(v.x, h0, l0); split(v.y, h1, l1);
                split(v.z, h2, l2); split(v.w, h3, l3);
                int kw = o * 8 + q * 2;
                ah[swz(kw, m)]     = pack_bf2(h0, h1);
                ah[swz(kw + 1, m)] = pack_bf2(h2, h3);
                al[swz(kw, m)]     = pack_bf2(l0, l1);
                al[swz(kw + 1, m)] = pack_bf2(l2, l3);
            }
        } else {
            #pragma unroll
            for (int q = 0; q < 4; q++) {
                int kw = o * 8 + q * 2;
                ah[swz(kw, m)] = 0;  ah[swz(kw + 1, m)] = 0;
                al[swz(kw, m)] = 0;  al[swz(kw + 1, m)] = 0;
            }
        }
    }
    // ---- stage W^T -> Bh/Bl (thread owns column n, 32 k values) ----
    {
        const int n  = tid & 127;
        const int kq = (tid >> 7) * 32;
        const float* wp = W + (size_t)e * D * D + (size_t)kq * D + n;
        uint32_t* bh = Bh + n * 64;
        uint32_t* bl = Bl + n * 64;
        #pragma unroll
        for (int kk = 0; kk < 16; kk++) {
            float v0 = wp[(2 * kk) * D];
            float v1 = wp[(2 * kk + 1) * D];
            __nv_bfloat16 h0, h1, l0, l1;
            split(v0, h0, l0); split(v1, h1, l1);
            int kw = kq / 2 + kk;
            bh[swz(kw, n)] = pack_bf2(h0, h1);
            bl[swz(kw, n)] = pack_bf2(l0, l1);
        }
    }
    __syncthreads();

    // ---- mainloop: 4m x 4n warps; warp tile 16x32; ldmatrix fragments ----
    const int wm = (wid & 3) * 16;
    const int wn = (wid >> 2) * 32;
    const int g = lane >> 2, cq = lane & 3;

    // ldmatrix lane geometry
    const int t = lane >> 3, r = lane & 7;
    const int m_l = wm + (t & 1) * 8 + r;
    const int ka  = (t >> 1) * 4;
    const int xa  = (m_l & 15) << 2;
    const uint32_t aBaseH = sb + SM_AH + m_l * 256;
    const uint32_t aBaseL = sb + SM_AL + m_l * 256;

    const int n_l0 = wn + (t >> 1) * 8 + r;
    const int n_l1 = n_l0 + 16;
    const int kb   = (t & 1) * 4;
    const int xb0  = (n_l0 & 15) << 2;
    const int xb1  = (n_l1 & 15) << 2;
    const uint32_t b0BaseH = sb + SM_BH + n_l0 * 256;
    const uint32_t b1BaseH = sb + SM_BH + n_l1 * 256;
    const uint32_t b0BaseL = sb + SM_BL + n_l0 * 256;
    const uint32_t b1BaseL = sb + SM_BL + n_l1 * 256;

    float acc[4][4];
    #pragma unroll
    for (int nt = 0; nt < 4; nt++)
        #pragma unroll
        for (int j = 0; j < 4; j++) acc[nt][j] = 0.f;

    #pragma unroll
    for (int ks = 0; ks < 8; ks++) {
        const int k0w = ks * 8;
        const uint32_t wa  = (uint32_t)(((k0w + ka) ^ xa) * 4);
        const uint32_t wb0 = (uint32_t)(((k0w + kb) ^ xb0) * 4);
        const uint32_t wb1 = (uint32_t)(((k0w + kb) ^ xb1) * 4);

        uint32_t ah[4], al[4], bh[8], bl[8];
        ldsm4(ah, aBaseH + wa);
        ldsm4(al, aBaseL + wa);
        ldsm4(bh,     b0BaseH + wb0);   // nt0: b0,b1 ; nt1: b0,b1
        ldsm4(bh + 4, b1BaseH + wb1);   // nt2, nt3
        ldsm4(bl,     b0BaseL + wb0);
        ldsm4(bl + 4, b1BaseL + wb1);

        #pragma unroll
        for (int nt = 0; nt < 4; nt++)
            mma16(acc[nt], ah, bh[2 * nt], bh[2 * nt + 1]);   // hh
        #pragma unroll
        for (int nt = 0; nt < 4; nt++)
            mma16(acc[nt], ah, bl[2 * nt], bl[2 * nt + 1]);   // hl
        #pragma unroll
        for (int nt = 0; nt < 4; nt++)
            mma16(acc[nt], al, bh[2 * nt], bh[2 * nt + 1]);   // lh
    }

    // ---- epilogue ----
    #pragma unroll
    for (int rp = 0; rp < 2; rp++) {
        const int row = wm + g + rp * 8;
        const int tok = idxs[row];
        if (tok < 0) continue;
        float* yr = Y + (size_t)tok * D;
        #pragma unroll
        for (int nt = 0; nt < 4; nt++) {
            const int col = wn + nt * 8 + 2 * cq;
            float2 o;
            o.x = acc[nt][rp * 2 + 0] + sB[col];
            o.y = acc[nt][rp * 2 + 1] + sB[col + 1];
            *(float2*)(yr + col) = o;
        }
    }
}

extern "C" void kernel_launch(void* const* d_in, const int* in_sizes, int n_in,
                              void* d_out, int out_size) {
    const int*   positions = (const int*)d_in[0];
    const float* X  = (const float*)d_in[1];
    const float* W  = (const float*)d_in[2];
    const float* Bv = (const float*)d_in[3];
    float* Y = (float*)d_out;

    cudaFuncSetAttribute(fused_kernel,
                         cudaFuncAttributeMaxDynamicSharedMemorySize, SM_TOT);

    dim3 grid(NEXP, NTOK / MT);
    fused_kernel<<<grid, NT_THREADS, SM_TOT>>>(positions, X, W, Bv, Y);
}

// round 17
// speedup vs baseline: 2.7373x; 1.0017x over previous
#include <cuda_runtime.h>
#include <cuda_bf16.h>
#include <cstdint>

#define NTOK   8192
#define D      128
#define NEXP   9
#define MT     64
#define NT_THREADS 512
#define BKT    1024
#define GEMM_GRID 136          // worst-case sum of per-expert tiles

__device__ int g_counts[NEXP];
__device__ int g_bkt[NTOK];

// ---------------- single-block bucketing: all experts, registers only --------
__global__ __launch_bounds__(BKT) void bucket_kernel(const int* __restrict__ positions) {
    __shared__ int wtot[NEXP][32];
    __shared__ int wpre[NEXP][32];
    __shared__ int ebase[NEXP];
    __shared__ int etot[NEXP];
    const int tid = threadIdx.x, lane = tid & 31, wid = tid >> 5;

    int id[8];
    {
        const int4* pp = (const int4*)(positions + tid * 8);
        int4 v0 = pp[0], v1 = pp[1];
        id[0] = v0.x; id[1] = v0.y; id[2] = v0.z; id[3] = v0.w;
        id[4] = v1.x; id[5] = v1.y; id[6] = v1.z; id[7] = v1.w;
        #pragma unroll
        for (int i = 0; i < 8; i++) id[i] = min(max(id[i], 0), NEXP - 1);
    }

    uint32_t mask[NEXP]; int ex[NEXP];
    #pragma unroll
    for (int e = 0; e < NEXP; e++) {
        uint32_t m = 0;
        #pragma unroll
        for (int i = 0; i < 8; i++) if (id[i] == e) m |= 1u << i;
        mask[e] = m;
        int c = __popc(m), s = c;
        #pragma unroll
        for (int off = 1; off < 32; off <<= 1) {
            int u = __shfl_up_sync(0xFFFFFFFFu, s, off);
            if (lane >= off) s += u;
        }
        ex[e] = s - c;
        if (lane == 31) wtot[e][wid] = s;
    }
    __syncthreads();

    if (wid < NEXP) {                      // warp w scans expert w across 32 warps
        int v = wtot[wid][lane], s = v;
        #pragma unroll
        for (int off = 1; off < 32; off <<= 1) {
            int u = __shfl_up_sync(0xFFFFFFFFu, s, off);
            if (lane >= off) s += u;
        }
        wpre[wid][lane] = s - v;
        if (lane == 31) etot[wid] = s;
    }
    __syncthreads();

    if (tid == 0) {
        int run = 0;
        #pragma unroll
        for (int e = 0; e < NEXP; e++) {
            ebase[e] = run;
            g_counts[e] = etot[e];
            run += etot[e];
        }
    }
    __syncthreads();

    #pragma unroll
    for (int e = 0; e < NEXP; e++) {
        int rank = ebase[e] + wpre[e][wid] + ex[e];
        uint32_t m = mask[e];
        #pragma unroll
        for (int i = 0; i < 8; i++) {
            if ((m >> i) & 1u) g_bkt[rank++] = tid * 8 + i;
        }
    }
}

// ---------------- GEMM helpers (verified round-14 path) ----------------------
#define SM_AH   0
#define SM_AL   16384
#define SM_BH   32768
#define SM_BL   65536
#define SM_IDX  98304
#define SM_BIAS 98560
#define SM_CNT  99072               // 9 ints
#define SM_TOT  99328

__device__ __forceinline__ int swz(int kw, int row) { return kw ^ ((row & 15) << 2); }
__device__ __forceinline__ uint32_t pack_bf2(__nv_bfloat16 a, __nv_bfloat16 b) {
    __nv_bfloat162 t; t.x = a; t.y = b;
    return *(uint32_t*)&t;
}
__device__ __forceinline__ void split(float v, __nv_bfloat16& h, __nv_bfloat16& l) {
    h = __float2bfloat16(v);
    l = __float2bfloat16(v - __bfloat162float(h));
}
__device__ __forceinline__ void mma16(float* d, const uint32_t* a, uint32_t b0, uint32_t b1) {
    asm volatile(
        "mma.sync.aligned.m16n8k16.row.col.f32.bf16.bf16.f32 "
        "{%0,%1,%2,%3}, {%4,%5,%6,%7}, {%8,%9}, {%0,%1,%2,%3};"
        : "+f"(d[0]), "+f"(d[1]), "+f"(d[2]), "+f"(d[3])
        : "r"(a[0]), "r"(a[1]), "r"(a[2]), "r"(a[3]), "r"(b0), "r"(b1));
}
__device__ __forceinline__ void ldsm4(uint32_t* r, uint32_t addr) {
    asm volatile("ldmatrix.sync.aligned.m8n8.x4.shared.b16 {%0,%1,%2,%3}, [%4];"
        : "=r"(r[0]), "=r"(r[1]), "=r"(r[2]), "=r"(r[3]) : "r"(addr));
}
__device__ __forceinline__ uint32_t smem_u32(const void* p) {
    uint32_t a;
    asm("{ .reg .u64 t; cvta.to.shared.u64 t, %1; cvt.u32.u64 %0, t; }" : "=r"(a) : "l"(p));
    return a;
}

__global__ __launch_bounds__(NT_THREADS, 2) void gemm_kernel(
    const float* __restrict__ X, const float* __restrict__ W,
    const float* __restrict__ Bv, float* __restrict__ Y)
{
    extern __shared__ char smem[];
    const uint32_t sb = smem_u32(smem);
    uint32_t* Ah = (uint32_t*)(smem + SM_AH);
    uint32_t* Al = (uint32_t*)(smem + SM_AL);
    uint32_t* Bh = (uint32_t*)(smem + SM_BH);
    uint32_t* Bl = (uint32_t*)(smem + SM_BL);
    int*   idxs = (int*)(smem + SM_IDX);
    float* sB   = (float*)(smem + SM_BIAS);
    int*   scnt = (int*)(smem + SM_CNT);

    const int tid = threadIdx.x, lane = tid & 31, wid = tid >> 5;

    if (tid < NEXP) scnt[tid] = g_counts[tid];
    __syncthreads();

    // map block id -> (expert, tile window)
    int e = 0, cnt = 0, base = 0, rem = blockIdx.x;
    bool found = false;
    #pragma unroll
    for (int q = 0; q < NEXP; q++) {
        int cq = scnt[q];
        int nt = (cq + MT - 1) >> 6;
        if (!found) {
            if (rem < nt) { found = true; e = q; cnt = cq; }
            else          { rem -= nt; base += cq; }
        }
    }
    if (!found) return;
    const int m0 = rem * MT;

    if (tid < MT)
        idxs[tid] = (m0 + tid < cnt) ? g_bkt[base + m0 + tid] : -1;
    if (tid >= NT_THREADS - 32)
        ((float4*)sB)[tid - (NT_THREADS - 32)] =
            ((const float4*)(Bv + e * D))[tid - (NT_THREADS - 32)];
    __syncthreads();

    // ---- stage X -> Ah/Al (8 threads per row) ----
    {
        const int m = tid >> 3, o = tid & 7;
        const int tok = idxs[m];
        uint32_t* ah = Ah + m * 64;
        uint32_t* al = Al + m * 64;
        if (tok >= 0) {
            const float4* xr = (const float4*)(X + (size_t)tok * D + o * 16);
            #pragma unroll
            for (int q = 0; q < 4; q++) {
                float4 v = xr[q];
                __nv_bfloat16 h0, h1, h2, h3, l0, l1, l2, l3;
                split(v.x, h0, l0); split(v.y, h1, l1);
                split(v.z, h2, l2); split(v.w, h3, l3);
                int kw = o * 8 + q * 2;
                ah[swz(kw, m)]     = pack_bf2(h0, h1);
                ah[swz(kw + 1, m)] = pack_bf2(h2, h3);
                al[swz(kw, m)]     = pack_bf2(l0, l1);
                al[swz(kw + 1, m)] = pack_bf2(l2, l3);
            }
        } else {
            #pragma unroll
            for (int q = 0; q < 4; q++) {
                int kw = o * 8 + q * 2;
                ah[swz(kw, m)] = 0;  ah[swz(kw + 1, m)] = 0;
                al[swz(kw, m)] = 0;  al[swz(kw + 1, m)] = 0;
            }
        }
    }
    // ---- stage W^T -> Bh/Bl ----
    {
        const int n  = tid & 127;
        const int kq = (tid >> 7) * 32;
        const float* wp = W + (size_t)e * D * D + (size_t)kq * D + n;
        uint32_t* bh = Bh + n * 64;
        uint32_t* bl = Bl + n * 64;
        #pragma unroll
        for (int kk = 0; kk < 16; kk++) {
            float v0 = wp[(2 * kk) * D];
            float v1 = wp[(2 * kk + 1) * D];
            __nv_bfloat16 h0, h1, l0, l1;
            split(v0, h0, l0); split(v1, h1, l1);
            int kw = kq / 2 + kk;
            bh[swz(kw, n)] = pack_bf2(h0, h1);
            bl[swz(kw, n)] = pack_bf2(l0, l1);
        }
    }
    __syncthreads();

    // ---- mainloop: 4m x 4n warps; warp tile 16x32; ldmatrix fragments ----
    const int wm = (wid & 3) * 16;
    const int wn = (wid >> 2) * 32;
    const int g = lane >> 2, cq = lane & 3;

    const int t = lane >> 3, r = lane & 7;
    const int m_l = wm + (t & 1) * 8 + r;
    const int ka  = (t >> 1) * 4;
    const int xa  = (m_l & 15) << 2;
    const uint32_t aBaseH = sb + SM_AH + m_l * 256;
    const uint32_t aBaseL = sb + SM_AL + m_l * 256;

    const int n_l0 = wn + (t >> 1) * 8 + r;
    const int n_l1 = n_l0 + 16;
    const int kb   = (t & 1) * 4;
    const int xb0  = (n_l0 & 15) << 2;
    const int xb1  = (n_l1 & 15) << 2;
    const uint32_t b0BaseH = sb + SM_BH + n_l0 * 256;
    const uint32_t b1BaseH = sb + SM_BH + n_l1 * 256;
    const uint32_t b0BaseL = sb + SM_BL + n_l0 * 256;
    const uint32_t b1BaseL = sb + SM_BL + n_l1 * 256;

    float acc[4][4];
    #pragma unroll
    for (int nt = 0; nt < 4; nt++)
        #pragma unroll
        for (int j = 0; j < 4; j++) acc[nt][j] = 0.f;

    #pragma unroll
    for (int ks = 0; ks < 8; ks++) {
        const int k0w = ks * 8;
        const uint32_t wa  = (uint32_t)(((k0w + ka) ^ xa) * 4);
        const uint32_t wb0 = (uint32_t)(((k0w + kb) ^ xb0) * 4);
        const uint32_t wb1 = (uint32_t)(((k0w + kb) ^ xb1) * 4);

        uint32_t ah[4], al[4], bh[8], bl[8];
        ldsm4(ah, aBaseH + wa);
        ldsm4(al, aBaseL + wa);
        ldsm4(bh,     b0BaseH + wb0);
        ldsm4(bh + 4, b1BaseH + wb1);
        ldsm4(bl,     b0BaseL + wb0);
        ldsm4(bl + 4, b1BaseL + wb1);

        #pragma unroll
        for (int nt = 0; nt < 4; nt++)
            mma16(acc[nt], ah, bh[2 * nt], bh[2 * nt + 1]);   // hh
        #pragma unroll
        for (int nt = 0; nt < 4; nt++)
            mma16(acc[nt], ah, bl[2 * nt], bl[2 * nt + 1]);   // hl
        #pragma unroll
        for (int nt = 0; nt < 4; nt++)
            mma16(acc[nt], al, bh[2 * nt], bh[2 * nt + 1]);   // lh
    }

    // ---- epilogue ----
    #pragma unroll
    for (int rp = 0; rp < 2; rp++) {
        const int row = wm + g + rp * 8;
        const int tok = idxs[row];
        if (tok < 0) continue;
        float* yr = Y + (size_t)tok * D;
        #pragma unroll
        for (int nt = 0; nt < 4; nt++) {
            const int col = wn + nt * 8 + 2 * cq;
            float2 o;
            o.x = acc[nt][rp * 2 + 0] + sB[col];
            o.y = acc[nt][rp * 2 + 1] + sB[col + 1];
            *(float2*)(yr + col) = o;
        }
    }
}

extern "C" void kernel_launch(void* const* d_in, const int* in_sizes, int n_in,
                              void* d_out, int out_size) {
    const int*   positions = (const int*)d_in[0];
    const float* X  = (const float*)d_in[1];
    const float* W  = (const float*)d_in[2];
    const float* Bv = (const float*)d_in[3];
    float* Y = (float*)d_out;

    cudaFuncSetAttribute(gemm_kernel,
                         cudaFuncAttributeMaxDynamicSharedMemorySize, SM_TOT);

    bucket_kernel<<<1, BKT>>>(positions);
    gemm_kernel<<<GEMM_GRID, NT_THREADS, SM_TOT>>>(X, W, Bv, Y);
}